// round 1
// baseline (speedup 1.0000x reference)
#include <cuda_runtime.h>
#include <cstdint>

#define D_DIM 4096
#define K_SEL 2048
#define NT    256
#define FULL  0xFFFFFFFFu

__global__ __launch_bounds__(NT)
void topk_mask_kernel(const float* __restrict__ x, float* __restrict__ out) {
    __shared__ float cand[D_DIM];     // candidate values (worst-case: whole row)
    __shared__ float gbuf[32];        // final gather buffer
    __shared__ int   s_cnt[16];       // per-warp partial counts (8 hi, 8 lo)
    __shared__ int   s_m;             // candidate count
    __shared__ int   s_chi;           // count of x >= B (above-bracket)
    __shared__ int   s_ok;            // bracket validity flag
    __shared__ float s_T;             // selected threshold

    const int tid  = threadIdx.x;
    const int wid  = tid >> 5;
    const int lane = tid & 31;
    const size_t row = blockIdx.x;

    const float4* xin  = reinterpret_cast<const float4*>(x   + row * D_DIM);
    float4*       xout = reinterpret_cast<float4*>      (out + row * D_DIM);

    // ---- load 16 elements per thread (coalesced float4, streaming) ----
    float vals[16];
#pragma unroll
    for (int i = 0; i < 4; i++) {
        float4 v = __ldcs(xin + i * NT + tid);
        vals[4*i+0] = v.x; vals[4*i+1] = v.y;
        vals[4*i+2] = v.z; vals[4*i+3] = v.w;
    }

    // ---- bracket the median: count above/below [-B, B), widen if invalid ----
    float B = 0.15f;   // 7.7 sigma of the sample-median distribution
    for (int attempt = 0; attempt < 24; attempt++) {
        int chi = 0, clo = 0;
#pragma unroll
        for (int i = 0; i < 16; i++) {
            chi += (vals[i] >=  B);
            clo += (vals[i] >= -B);
        }
        chi = __reduce_add_sync(FULL, chi);
        clo = __reduce_add_sync(FULL, clo);
        if (lane == 0) { s_cnt[wid] = chi; s_cnt[8 + wid] = clo; }
        __syncthreads();
        if (tid == 0) {
            int H = 0, L = 0;
#pragma unroll
            for (int w = 0; w < 8; w++) { H += s_cnt[w]; L += s_cnt[8 + w]; }
            s_chi = H;
            s_m   = 0;
            s_ok  = (H < K_SEL) && (K_SEL <= L);
        }
        __syncthreads();
        if (s_ok) break;
        B *= 2.0f;                    // ultra-rare widening path (exact fallback)
    }

    // ---- compact candidates in [-B, B) to smem (warp-aggregated pushes) ----
#pragma unroll
    for (int i = 0; i < 16; i++) {
        bool p = (vals[i] >= -B) && (vals[i] < B);
        unsigned mk = __ballot_sync(FULL, p);
        int cnt = __popc(mk);
        if (cnt) {
            int base = 0;
            if (lane == 0) base = atomicAdd(&s_m, cnt);
            base = __shfl_sync(FULL, base, 0);
            if (p) cand[base + __popc(mk & ((1u << lane) - 1u))] = vals[i];
        }
    }
    __syncthreads();

    // ---- one warp: exact rank-select among candidates ----
    if (wid == (int)(row & 7)) {
        const int m  = s_m;
        const int rp = K_SEL - s_chi;       // 1-based rank (from top) within candidates
        float lo = -B, hi = B;
        int clo = m, chi2 = 0;              // counts of cand >= lo / >= hi
        int  degenerate = 0;

        // value-domain bisection: density ~uniform near 0 -> halves live set per iter
        for (int it = 0; (clo - chi2 > 32) && (it < 64); it++) {
            float mid = 0.5f * (lo + hi);
            if (mid == lo || mid == hi) { degenerate = 1; break; }
            int c = 0;
            for (int base = 0; base < m; base += 32) {
                int i = base + lane;
                c += (i < m) && (cand[i] >= mid);
            }
            c = __reduce_add_sync(FULL, c);
            if (c >= rp) { lo = mid; clo = c; } else { hi = mid; chi2 = c; }
        }

        const int b = clo - chi2;           // survivors in [lo, hi)
        if (degenerate || b > 32) {
            if (lane == 0) s_T = lo;        // duplicate-collapse fallback (keeps >= k, ties)
        } else {
            // gather the b survivors
            int pos = 0;
            for (int base = 0; base < m; base += 32) {
                int i = base + lane;
                float u = (i < m) ? cand[i] : 0.0f;
                bool p = (i < m) && (u >= lo) && (u < hi);
                unsigned mk = __ballot_sync(FULL, p);
                if (p) gbuf[pos + __popc(mk & ((1u << lane) - 1u))] = u;
                pos += __popc(mk);
            }
            __syncwarp();
            float gv = (lane < b) ? gbuf[lane] : __int_as_float(0xff800000); // -inf
            int gt = 0, eq = 0;
#pragma unroll
            for (int d = 1; d < 32; d++) {
                float o = __shfl_sync(FULL, gv, (lane + d) & 31);
                gt += (o > gv);
                eq += (o == gv);
            }
            const int j = rp - chi2;        // 1-based target among gathered
            if ((lane < b) && (gt < j) && (gt + eq + 1 >= j)) s_T = gv;
        }
    }
    __syncthreads();

    // ---- apply mask and write (streaming float4 stores) ----
    const float tf = s_T;
#pragma unroll
    for (int i = 0; i < 4; i++) {
        float4 w;
        w.x = (vals[4*i+0] >= tf) ? vals[4*i+0] : 0.0f;
        w.y = (vals[4*i+1] >= tf) ? vals[4*i+1] : 0.0f;
        w.z = (vals[4*i+2] >= tf) ? vals[4*i+2] : 0.0f;
        w.w = (vals[4*i+3] >= tf) ? vals[4*i+3] : 0.0f;
        __stcs(xout + i * NT + tid, w);
    }
}

extern "C" void kernel_launch(void* const* d_in, const int* in_sizes, int n_in,
                              void* d_out, int out_size) {
    const float* x = (const float*)d_in[0];
    float* out = (float*)d_out;
    int n = in_sizes[0];
    int rows = n / D_DIM;                 // 16384 for (4, 4096, 4096)
    topk_mask_kernel<<<rows, NT>>>(x, out);
}

// round 2
// speedup vs baseline: 1.5229x; 1.5229x over previous
#include <cuda_runtime.h>
#include <cstdint>

#define D_DIM 4096
#define K_SEL 2048
#define NT    512
#define EPT   8            // elements per thread (2x float4)
#define FULL  0xFFFFFFFFu
#define NCNT  64           // smem counter slots
#define CAP   64           // survivor buffer capacity

__global__ __launch_bounds__(NT, 4)
void topk_mask_kernel(const float* __restrict__ x, float* __restrict__ out) {
    __shared__ int   s_cnt[NCNT];   // atomic counters (one slot per count round)
    __shared__ int   s_m;           // survivor count
    __shared__ float gbuf[CAP];     // survivor values
    __shared__ float s_T;           // selected threshold

    const int tid  = threadIdx.x;
    const int lane = tid & 31;
    const size_t row = blockIdx.x;

    const float4* xin  = reinterpret_cast<const float4*>(x   + row * D_DIM);
    float4*       xout = reinterpret_cast<float4*>      (out + row * D_DIM);

    if (tid < NCNT) s_cnt[tid] = 0;
    if (tid == NCNT) s_m = 0;

    // ---- load 8 elements per thread (coalesced float4, streaming) ----
    float vals[EPT];
#pragma unroll
    for (int i = 0; i < 2; i++) {
        float4 v = __ldcs(xin + i * NT + tid);
        vals[4*i+0] = v.x; vals[4*i+1] = v.y;
        vals[4*i+2] = v.z; vals[4*i+3] = v.w;
    }

    // ---- bracket the k-th value: count >= B and >= -B; widen if invalid ----
    // median of 4096 N(0,1) samples has sigma ~0.0196; 0.15 = 7.7 sigma.
    float B = 0.15f;
    int CHI = 0, CLO = 0;
    for (int a = 0; a < 12; a++) {
        int chi = 0, clo = 0;
#pragma unroll
        for (int i = 0; i < EPT; i++) {
            chi += (vals[i] >=  B);
            clo += (vals[i] >= -B);
        }
        chi = __reduce_add_sync(FULL, chi);
        clo = __reduce_add_sync(FULL, clo);
        if (lane == 0) {
            atomicAdd(&s_cnt[2*a],     chi);
            atomicAdd(&s_cnt[2*a + 1], clo);
        }
        __syncthreads();
        CHI = s_cnt[2*a];
        CLO = s_cnt[2*a + 1];
        if (CHI < K_SEL && K_SEL <= CLO) break;   // fast path: first try
        B *= 2.0f;                                 // ultra-rare widening
    }

    // ---- block-parallel interpolated search: shrink live set to <= 32 ----
    // invariant: cnt(>=lo) = clo >= K, cnt(>=hi) = chi < K
    float lo = -B, hi = B;
    int clo = CLO, chi = CHI;
    int it = 0, deg = 0;
    while (clo - chi > 32) {
        if (it >= 18) { deg = 1; break; }
        // regula falsi: density ~uniform near median -> 1-2 probes suffice
        float t = (float)(clo - K_SEL) / (float)(clo - chi);
        t = fminf(fmaxf(t, 0.10f), 0.90f);         // guaranteed progress
        float mid = lo + t * (hi - lo);
        if (mid <= lo || mid >= hi) { deg = 1; break; }
        int c = 0;
#pragma unroll
        for (int i = 0; i < EPT; i++) c += (vals[i] >= mid);
        c = __reduce_add_sync(FULL, c);
        if (lane == 0) atomicAdd(&s_cnt[24 + it], c);
        __syncthreads();
        c = s_cnt[24 + it];
        if (c >= K_SEL) { lo = mid; clo = c; }
        else            { hi = mid; chi = c; }
        it++;
    }

    if (deg) {
        if (tid == 0) s_T = lo;   // duplicate-collapse fallback (keeps >= k)
        __syncthreads();
    } else {
        // ---- compact the <=32 survivors in [lo, hi) ----
#pragma unroll
        for (int i = 0; i < EPT; i++) {
            bool p = (vals[i] >= lo) && (vals[i] < hi);
            unsigned mk = __ballot_sync(FULL, p);
            int cnt = __popc(mk);
            if (cnt) {
                int base = 0;
                if (lane == 0) base = atomicAdd(&s_m, cnt);
                base = __shfl_sync(FULL, base, 0);
                int idx = base + __popc(mk & ((1u << lane) - 1u));
                if (p && idx < CAP) gbuf[idx] = vals[i];
            }
        }
        __syncthreads();

        // ---- warp 0: exact rank among survivors via all-pairs shuffle ----
        if (tid < 32) {
            const int b = s_m;                    // == clo - chi (<= 32)
            const int j = K_SEL - chi;            // 1-based target rank in gbuf
            float gv = (lane < b) ? gbuf[lane] : __int_as_float(0xff800000);
            int gt = 0, eq = 0;
#pragma unroll
            for (int d = 1; d < 32; d++) {
                float o = __shfl_sync(FULL, gv, (lane + d) & 31);
                gt += (o > gv);
                eq += (o == gv);
            }
            if ((lane < b) && (gt < j) && (gt + eq + 1 >= j)) s_T = gv;
            if (b > CAP && lane == 0) s_T = lo;   // impossible-path guard
        }
        __syncthreads();
    }

    // ---- apply mask and write (streaming float4 stores) ----
    const float tf = s_T;
#pragma unroll
    for (int i = 0; i < 2; i++) {
        float4 w;
        w.x = (vals[4*i+0] >= tf) ? vals[4*i+0] : 0.0f;
        w.y = (vals[4*i+1] >= tf) ? vals[4*i+1] : 0.0f;
        w.z = (vals[4*i+2] >= tf) ? vals[4*i+2] : 0.0f;
        w.w = (vals[4*i+3] >= tf) ? vals[4*i+3] : 0.0f;
        __stcs(xout + i * NT + tid, w);
    }
}

extern "C" void kernel_launch(void* const* d_in, const int* in_sizes, int n_in,
                              void* d_out, int out_size) {
    const float* x = (const float*)d_in[0];
    float* out = (float*)d_out;
    int n = in_sizes[0];
    int rows = n / D_DIM;                 // 16384 for (4, 4096, 4096)
    topk_mask_kernel<<<rows, NT>>>(x, out);
}